// round 16
// baseline (speedup 1.0000x reference)
#include <cuda_runtime.h>
#include <cuda_fp16.h>

// Bilinear_89361089561016: 3D grid_sample, trilinear, border padding,
// align_corners=False.  B=2, C=1, X=Y=Z=160.
//
// Round 16: full 2x2x2 fp16 corner cube (one branchless LDG.128 gather per
// output = 1.0 L1 wavefront, vs the quad layout's 1.5 with divergence),
// combined with the R15 ILP structure (4 outputs/thread, float4 streams).
// Single 65.5MB scratch, sequential pack->sample per batch: producer lines
// are L2-resident for the consumer, and in steady-state graph replay the
// re-dirtied lines need not touch DRAM at all. Pack is z-innermost so its
// 16B stores coalesce naturally (no smem transpose needed).

#define DIM   160
#define DIM2  (DIM * DIM)                // 25,600
#define NVOX  (DIM * DIM * DIM)          // 4,096,000
#define NQ    (NVOX / 4)                 // threads per phase (4 z per thread)
#define NBLK  (NQ / 256)                 // 4000 blocks

// 65.5 MB: packed 2x2x2 fp16 corner cubes for ONE batch at a time.
__device__ uint4 g_cube[NVOX];

__device__ __forceinline__ unsigned int h2_to_u32(__half2 h) {
    return *reinterpret_cast<unsigned int*>(&h);
}
__device__ __forceinline__ __half2 u32_to_h2(unsigned int u) {
    return *reinterpret_cast<__half2*>(&u);
}
__device__ __forceinline__ unsigned int pack2(float a, float b) {
    return h2_to_u32(__floats2half2_rn(a, b));
}

// ---------------- pack: 4 consecutive z per thread ------------------------
// cube[(x*160+y)*160+z] = fp16 x8 of v[x..x1][y..y1][z..z1] (borders clamped)
__global__ __launch_bounds__(256) void pack_cube_kernel(
    const float* __restrict__ vol, int b)
{
    int t  = blockIdx.x * 256 + threadIdx.x;   // < NQ
    int z  = (t % 40) * 4;                     // 0,4,...,156 (16B-aligned rows)
    int xy = t / 40;                           // x*DIM + y
    int y  = xy % DIM;
    int x  = xy / DIM;

    const float* vb = vol + (long long)b * NVOX;
    int xo = (x < DIM - 1) ? DIM2 : 0;
    int yo = (y < DIM - 1) ? DIM  : 0;
    int zt = min(z + 4, DIM - 1);              // tail scalar (clamped)

    const float* r00 = vb + xy * DIM;
    const float* r01 = r00 + yo;
    const float* r10 = r00 + xo;
    const float* r11 = r00 + xo + yo;

    float4 f00 = __ldg(reinterpret_cast<const float4*>(r00 + z));
    float4 f01 = __ldg(reinterpret_cast<const float4*>(r01 + z));
    float4 f10 = __ldg(reinterpret_cast<const float4*>(r10 + z));
    float4 f11 = __ldg(reinterpret_cast<const float4*>(r11 + z));
    float  e00 = __ldg(r00 + zt);
    float  e01 = __ldg(r01 + zt);
    float  e10 = __ldg(r10 + zt);
    float  e11 = __ldg(r11 + zt);

    uint4* dst = g_cube + xy * DIM + z;        // consecutive 16B -> coalesced
    dst[0] = make_uint4(pack2(f00.x, f00.y), pack2(f01.x, f01.y),
                        pack2(f10.x, f10.y), pack2(f11.x, f11.y));
    dst[1] = make_uint4(pack2(f00.y, f00.z), pack2(f01.y, f01.z),
                        pack2(f10.y, f10.z), pack2(f11.y, f11.z));
    dst[2] = make_uint4(pack2(f00.z, f00.w), pack2(f01.z, f01.w),
                        pack2(f10.z, f10.w), pack2(f11.z, f11.w));
    dst[3] = make_uint4(pack2(f00.w, e00), pack2(f01.w, e01),
                        pack2(f10.w, e10), pack2(f11.w, e11));
}

// ---------------- sample: 4 outputs per thread ----------------------------
__device__ __forceinline__ float sample_one(float gx, float gy, float gz)
{
    // unnormalize + border clamp:  ((g+1)*160 - 1)*0.5 = 80*g + 79.5
    float cx = fminf(fmaxf(fmaf(gx, 80.0f, 79.5f), 0.0f), 159.0f);
    float cy = fminf(fmaxf(fmaf(gy, 80.0f, 79.5f), 0.0f), 159.0f);
    float cz = fminf(fmaxf(fmaf(gz, 80.0f, 79.5f), 0.0f), 159.0f);

    float x0f = floorf(cx), y0f = floorf(cy), z0f = floorf(cz);
    float wx = cx - x0f, wy = cy - y0f, wz = cz - z0f;

    int x0 = (int)x0f;
    int y0 = (int)y0f;
    int z0 = (int)z0f;

    // single 16B gather: all 8 corners, branchless, always aligned
    uint4 p = __ldg(&g_cube[(x0 * DIM + y0) * DIM + z0]);

    float2 a00 = __half22float2(u32_to_h2(p.x));  // (v000, v001)
    float2 a01 = __half22float2(u32_to_h2(p.y));  // (v010, v011)
    float2 a10 = __half22float2(u32_to_h2(p.z));  // (v100, v101)
    float2 a11 = __half22float2(u32_to_h2(p.w));  // (v110, v111)

    float c00 = fmaf(wz, a00.y - a00.x, a00.x);
    float c01 = fmaf(wz, a01.y - a01.x, a01.x);
    float c10 = fmaf(wz, a10.y - a10.x, a10.x);
    float c11 = fmaf(wz, a11.y - a11.x, a11.x);

    float p0 = fmaf(wy, c01 - c00, c00);
    float p1 = fmaf(wy, c11 - c10, c10);
    return fmaf(wx, p1 - p0, p0);
}

__global__ __launch_bounds__(256) void sample_kernel(
    const float* __restrict__ grid, float* __restrict__ out, int b)
{
    int e = (blockIdx.x * 256 + threadIdx.x) * 4;   // element base

    const float* g = grid + (long long)b * 3 * NVOX + e;
    float4 gx = __ldcs(reinterpret_cast<const float4*>(g));
    float4 gy = __ldcs(reinterpret_cast<const float4*>(g + NVOX));
    float4 gz = __ldcs(reinterpret_cast<const float4*>(g + 2 * NVOX));

    float4 o;
    o.x = sample_one(gx.x, gy.x, gz.x);
    o.y = sample_one(gx.y, gy.y, gz.y);
    o.z = sample_one(gx.z, gy.z, gz.z);
    o.w = sample_one(gx.w, gy.w, gz.w);

    __stcs(reinterpret_cast<float4*>(out + (long long)b * NVOX + e), o);
}

extern "C" void kernel_launch(void* const* d_in, const int* in_sizes, int n_in,
                              void* d_out, int out_size)
{
    const float* vol  = (const float*)d_in[0];   // input1 [2,1,160,160,160]
    const float* grid = (const float*)d_in[1];   // input2 [2,3,160,160,160]
    float* out = (float*)d_out;

    pack_cube_kernel<<<NBLK, 256>>>(vol, 0);
    sample_kernel   <<<NBLK, 256>>>(grid, out, 0);
    pack_cube_kernel<<<NBLK, 256>>>(vol, 1);
    sample_kernel   <<<NBLK, 256>>>(grid, out, 1);
}

// round 17
// speedup vs baseline: 1.0553x; 1.0553x over previous
#include <cuda_runtime.h>
#include <cuda_fp16.h>

// Bilinear_89361089561016: 3D grid_sample, trilinear, border padding,
// align_corners=False.  B=2, C=1, X=Y=Z=160.
//
// Round 17: back to the proven quad layout (R16's 16B/voxel cube thrashed
// L2 and doubled pack traffic). Changes vs R15 (76.5us):
//  - SINGLE 32.8MB packed buffer, sequential pack->sample per batch:
//    during each sample pass only 32.8MB competes with the grid stream for
//    L2 (R15 kept 65.6MB -> ~50MB DRAM misses per merged sample pass).
//  - pack stage vectorized: smem stride 33 -> 44 floats (rows 16B-aligned,
//    emit conflicts still 2-way) so staging writes STS.128, not 4x STS.
//  - sample: unchanged R15 form (4 outputs/thread, float4 streams,
//    parity-fused gathers ~1.5 L1 wf/output, fp16 corners + fp32 lerp).

#define DIM   160
#define DIM2  (DIM * DIM)                // 25,600
#define NVOX  (DIM * DIM * DIM)          // 4,096,000

// 32.8MB, uint4 => guaranteed 16B base alignment (one batch at a time)
__device__ uint4 g_packed[NVOX / 2];

__device__ __forceinline__ unsigned int h2_to_u32(__half2 h) {
    return *reinterpret_cast<unsigned int*>(&h);
}
__device__ __forceinline__ __half2 u32_to_h2(unsigned int u) {
    return *reinterpret_cast<__half2*>(&u);
}
__device__ __forceinline__ unsigned int pack2(float a, float b) {
    return h2_to_u32(__floats2half2_rn(a, b));
}

// ---------------- tiled pack (smem transpose, vectorized STS) -------------
// One block: (32x, 1y, 32z) tile. 64 staged rows (x_local*2 + dy) of 33
// clamped z-values, smem row stride 44 (16B-aligned, 2-way emit conflicts).
// Stage: 512 LDG.128 + STS.128 pairs + 64 tail scalars. Emit: 512 uint4
// stores (x-pair per store), coalesced 256B segments.
#define PACK_BLOCKS 4000                 // DIM * 5 * 5 per batch
struct PackSmem { float sv[64][44]; };   // 11.3KB

__global__ __launch_bounds__(256) void pack_kernel(
    const float* __restrict__ vol, int b)
{
    __shared__ PackSmem s;
    int p   = blockIdx.x;
    int tid = threadIdx.x;

    int y   = p / 25;
    int rem = p % 25;
    int z0  = (rem / 5) * 32;
    int x0  = (rem % 5) * 32;

    const float* vb = vol + (long long)b * NVOX;

    // stage: 64 rows x 8 float4 (z0..z0+31); both sides 16B-aligned
    #pragma unroll
    for (int it = tid; it < 512; it += 256) {
        int row = it >> 3;                // x_local*2 + dy
        int c   = it & 7;
        int xg  = x0 + (row >> 1);
        int yg  = min(y + (row & 1), DIM - 1);
        float4 f = __ldg(reinterpret_cast<const float4*>(
                             vb + (xg * DIM + yg) * DIM + z0) + c);
        *reinterpret_cast<float4*>(&s.sv[row][c * 4]) = f;
    }
    // tail: z0+32 (clamped at the far border)
    if (tid < 64) {
        int row = tid;
        int xg  = x0 + (row >> 1);
        int yg  = min(y + (row & 1), DIM - 1);
        int zg  = min(z0 + 32, DIM - 1);
        s.sv[row][32] = __ldg(vb + (xg * DIM + yg) * DIM + zg);
    }
    __syncthreads();

    // emit: 32 z rows x 16 x-pairs; lanes consecutive in xq -> coalesced
    #pragma unroll
    for (int it = tid; it < 512; it += 256) {
        int zl = it >> 4;
        int xq = it & 15;
        int r  = xq * 4;                  // rows for (2xq:y0,y1, 2xq+1:y0,y1)
        uint4 o;
        o.x = pack2(s.sv[r + 0][zl], s.sv[r + 0][zl + 1]);
        o.y = pack2(s.sv[r + 1][zl], s.sv[r + 1][zl + 1]);
        o.z = pack2(s.sv[r + 2][zl], s.sv[r + 2][zl + 1]);
        o.w = pack2(s.sv[r + 3][zl], s.sv[r + 3][zl + 1]);
        g_packed[(((y * DIM) + z0 + zl) * DIM + x0) / 2 + xq] = o;
    }
}

// ---------------- sample: 4 outputs per thread ----------------------------
__device__ __forceinline__ float sample_one(float gx, float gy, float gz)
{
    // unnormalize + border clamp:  ((g+1)*160 - 1)*0.5 = 80*g + 79.5
    float cx = fminf(fmaxf(fmaf(gx, 80.0f, 79.5f), 0.0f), 159.0f);
    float cy = fminf(fmaxf(fmaf(gy, 80.0f, 79.5f), 0.0f), 159.0f);
    float cz = fminf(fmaxf(fmaf(gz, 80.0f, 79.5f), 0.0f), 159.0f);

    float x0f = floorf(cx), y0f = floorf(cy), z0f = floorf(cz);
    float wx = cx - x0f, wy = cy - y0f, wz = cz - z0f;

    int x0 = (int)x0f;
    int y0 = (int)y0f;
    int z0 = (int)z0f;

    int idx = (y0 * DIM + z0) * DIM + x0;   // 8B-element index, x innermost
    const uint2* packed8 = reinterpret_cast<const uint2*>(g_packed);

    uint2 q0, q1;
    if ((x0 & 1) == 0) {
        uint4 tq = __ldg(g_packed + (idx >> 1));   // even: one 16B load
        q0 = make_uint2(tq.x, tq.y);
        q1 = make_uint2(tq.z, tq.w);
    } else {
        int dx = (x0 < DIM - 1) ? 1 : 0;           // x0=159 -> x1=159
        q0 = __ldg(packed8 + idx);
        q1 = __ldg(packed8 + idx + dx);
    }

    float2 a0 = __half22float2(u32_to_h2(q0.x));   // (v000, v001)
    float2 a1 = __half22float2(u32_to_h2(q0.y));   // (v010, v011)
    float2 b0 = __half22float2(u32_to_h2(q1.x));   // (v100, v101)
    float2 b1 = __half22float2(u32_to_h2(q1.y));   // (v110, v111)

    float c00 = fmaf(wz, a0.y - a0.x, a0.x);
    float c01 = fmaf(wz, a1.y - a1.x, a1.x);
    float c10 = fmaf(wz, b0.y - b0.x, b0.x);
    float c11 = fmaf(wz, b1.y - b1.x, b1.x);

    float p0 = fmaf(wy, c01 - c00, c00);
    float p1 = fmaf(wy, c11 - c10, c10);
    return fmaf(wx, p1 - p0, p0);
}

#define SBLK 4000                        // (NVOX/4) / 256 per batch

__global__ __launch_bounds__(256) void sample_kernel(
    const float* __restrict__ grid, float* __restrict__ out, int b)
{
    int e = (blockIdx.x * 256 + threadIdx.x) * 4;   // element base

    const float* g = grid + (long long)b * 3 * NVOX + e;
    float4 gx = __ldcs(reinterpret_cast<const float4*>(g));
    float4 gy = __ldcs(reinterpret_cast<const float4*>(g + NVOX));
    float4 gz = __ldcs(reinterpret_cast<const float4*>(g + 2 * NVOX));

    float4 o;
    o.x = sample_one(gx.x, gy.x, gz.x);
    o.y = sample_one(gx.y, gy.y, gz.y);
    o.z = sample_one(gx.z, gy.z, gz.z);
    o.w = sample_one(gx.w, gy.w, gz.w);

    __stcs(reinterpret_cast<float4*>(out + (long long)b * NVOX + e), o);
}

extern "C" void kernel_launch(void* const* d_in, const int* in_sizes, int n_in,
                              void* d_out, int out_size)
{
    const float* vol  = (const float*)d_in[0];   // input1 [2,1,160,160,160]
    const float* grid = (const float*)d_in[1];   // input2 [2,3,160,160,160]
    float* out = (float*)d_out;

    pack_kernel  <<<PACK_BLOCKS, 256>>>(vol, 0);
    sample_kernel<<<SBLK,        256>>>(grid, out, 0);
    pack_kernel  <<<PACK_BLOCKS, 256>>>(vol, 1);
    sample_kernel<<<SBLK,        256>>>(grid, out, 1);
}